// round 3
// baseline (speedup 1.0000x reference)
#include <cuda_runtime.h>
#include <cuda_bf16.h>
#include <math.h>

// Problem constants (fixed by the reference setup_inputs)
#define BB   8
#define NN   8192
#define MM   2048
#define C1   256
#define C2   256
#define CIN  512
#define HID  512

typedef unsigned long long u64;

// ---------------- scratch (device globals; no allocations allowed) ----------
__device__ float g_interp[(size_t)BB * C2 * NN];    // interpolated known feats (B,256,N)
__device__ float g_hidden[(size_t)BB * HID * NN];   // layer-1 output (B,512,N)
__device__ int   g_idx[(size_t)BB * NN * 3];
__device__ float g_w[(size_t)BB * NN * 3];

// ---------------- packed f32x2 helpers (FFMA2 path, sm_100+) ----------------
__device__ __forceinline__ u64 splat_f32x2(float x) {
    u64 r; asm("mov.b64 %0, {%1, %1};" : "=l"(r) : "f"(x)); return r;
}
__device__ __forceinline__ void ffma2(u64& d, u64 a, u64 b) {
    asm("fma.rn.f32x2 %0, %1, %2, %0;" : "+l"(d) : "l"(a), "l"(b));
}
__device__ __forceinline__ float2 unpack_f32x2(u64 v) {
    float2 r; asm("mov.b64 {%0, %1}, %2;" : "=f"(r.x), "=f"(r.y) : "l"(v)); return r;
}

// ============================================================================
// Kernel 1: brute-force 3-NN + inverse-distance weights
// grid (NN/256, B), 256 threads. Known points staged in smem (24 KB).
// ============================================================================
__global__ __launch_bounds__(256)
void knn3_kernel(const float* __restrict__ unknown, const float* __restrict__ known,
                 int* __restrict__ oidx, float* __restrict__ ow)
{
    __shared__ float sx[MM], sy[MM], sz[MM];
    const int b = blockIdx.y;
    const int i = blockIdx.x * 256 + threadIdx.x;

    const float* kb = known + (size_t)b * MM * 3;
    for (int j = threadIdx.x; j < MM; j += 256) {
        sx[j] = kb[j*3 + 0];
        sy[j] = kb[j*3 + 1];
        sz[j] = kb[j*3 + 2];
    }
    __syncthreads();

    const float* ub = unknown + ((size_t)b * NN + i) * 3;
    const float ux = ub[0], uy = ub[1], uz = ub[2];

    float d0 = 1e30f, d1 = 1e30f, d2 = 1e30f;
    int   j0 = 0,     j1 = 0,     j2 = 0;

    #pragma unroll 4
    for (int j = 0; j < MM; j++) {
        // exact fp32 sum-of-squares, no FMA contraction (match reference rounding)
        float dx = __fsub_rn(sx[j], ux);
        float dy = __fsub_rn(sy[j], uy);
        float dz = __fsub_rn(sz[j], uz);
        float d  = __fadd_rn(__fadd_rn(__fmul_rn(dx, dx), __fmul_rn(dy, dy)),
                             __fmul_rn(dz, dz));
        if (d < d2) {
            if (d < d1) {
                d2 = d1; j2 = j1;
                if (d < d0) { d1 = d0; j1 = j0; d0 = d; j0 = j; }
                else        { d1 = d;  j1 = j; }
            } else { d2 = d; j2 = j; }
        }
    }

    float r0 = 1.0f / (d0 + 1e-8f);
    float r1 = 1.0f / (d1 + 1e-8f);
    float r2 = 1.0f / (d2 + 1e-8f);
    float s  = (r0 + r1) + r2;

    size_t base = ((size_t)b * NN + i) * 3;
    oidx[base + 0] = j0;  oidx[base + 1] = j1;  oidx[base + 2] = j2;
    ow[base + 0] = r0 / s;  ow[base + 1] = r1 / s;  ow[base + 2] = r2 / s;
}

// ============================================================================
// Kernel 2: three_interpolate -> g_interp (B,256,N). Writes coalesced over i;
// gathers are 4B scattered but known_feats (16.8 MB) is L2-resident.
// ============================================================================
__global__ __launch_bounds__(256)
void interp_kernel(const float* __restrict__ kf,
                   const int* __restrict__ gidx, const float* __restrict__ gw,
                   float* __restrict__ X)
{
    const int b = blockIdx.y;
    const int i = blockIdx.x * 256 + threadIdx.x;

    size_t base = ((size_t)b * NN + i) * 3;
    const int   i0 = gidx[base], i1 = gidx[base + 1], i2 = gidx[base + 2];
    const float w0 = gw[base],   w1 = gw[base + 1],   w2 = gw[base + 2];

    const float* kfb = kf + (size_t)b * C2 * MM;
    float*       Xb  = X  + (size_t)b * C2 * NN;

    #pragma unroll 4
    for (int c = 0; c < C2; c++) {
        const float* row = kfb + (size_t)c * MM;
        Xb[(size_t)c * NN + i] = w0 * row[i0] + w1 * row[i1] + w2 * row[i2];
    }
}

// ============================================================================
// Kernel 3: SGEMM (M=512,N=8192,K=512) + fused BN + ReLU, packed f32x2 FMAs.
// C[b] = relu( BN( W @ Bsrc[b] ) ).  B-operand rows 0..255 come from Bsrc0,
// rows 256..511 from Bsrc1 (lets layer 1 fuse the concat away).
// 128x128 block tile, K-chunk 8, 256 threads, 8x8 microtile, double buffer.
// ============================================================================
#define TM 128
#define TN 128
#define TK 8

__global__ __launch_bounds__(256, 2)
void gemm_bn_relu_kernel(const float* __restrict__ W,        // [512,512] row-major
                         const float* __restrict__ Bsrc0,    // rows 0..255
                         const float* __restrict__ Bsrc1,    // rows 256..511
                         size_t bstride0, size_t bstride1,
                         const float* __restrict__ gamma, const float* __restrict__ beta,
                         const float* __restrict__ mean,  const float* __restrict__ var,
                         float* __restrict__ C)               // [B,512,NN]
{
    const int N = NN, K = CIN;
    const int b  = blockIdx.z;
    const int n0 = blockIdx.x * TN;
    const int m0 = blockIdx.y * TM;

    const float* B0b = Bsrc0 + (size_t)b * bstride0;
    const float* B1b = Bsrc1 + (size_t)b * bstride1;
    float*       Cb  = C     + (size_t)b * HID * N;

    __shared__ __align__(16) float As[2][TK][TM];
    __shared__ __align__(16) float Bs[2][TK][TN];

    const int tid  = threadIdx.x;
    const int arow = tid >> 1;          // 0..127
    const int acol = (tid & 1) * 4;     // 0 or 4
    const int brow = tid >> 5;          // 0..7
    const int bcol = (tid & 31) * 4;    // 0..124

    // ---- prologue: fetch chunk 0 ----
    float4 aReg = *(const float4*)(W + (size_t)(m0 + arow) * K + acol);
    {
        int gr = brow;
        const float* src = (gr < C2) ? (B0b + (size_t)gr * N)
                                     : (B1b + (size_t)(gr - C2) * N);
        float4 bReg = *(const float4*)(src + n0 + bcol);
        As[0][acol + 0][arow] = aReg.x;
        As[0][acol + 1][arow] = aReg.y;
        As[0][acol + 2][arow] = aReg.z;
        As[0][acol + 3][arow] = aReg.w;
        *(float4*)&Bs[0][brow][bcol] = bReg;
    }
    __syncthreads();

    const int ty = tid >> 4, tx = tid & 15;

    u64 acc[8][4];
    #pragma unroll
    for (int r = 0; r < 8; r++)
        #pragma unroll
        for (int p = 0; p < 4; p++) acc[r][p] = 0ull;

    float4 aNext; float4 bNext;
    const int NCHUNK = K / TK;   // 64
    for (int kc = 0; kc < NCHUNK; kc++) {
        const int buf = kc & 1;
        const bool more = (kc + 1 < NCHUNK);
        if (more) {
            const int k0 = (kc + 1) * TK;
            aNext = *(const float4*)(W + (size_t)(m0 + arow) * K + k0 + acol);
            int gr = k0 + brow;
            const float* src = (gr < C2) ? (B0b + (size_t)gr * N)
                                         : (B1b + (size_t)(gr - C2) * N);
            bNext = *(const float4*)(src + n0 + bcol);
        }

        #pragma unroll
        for (int kk = 0; kk < TK; kk++) {
            float4 a0 = *(const float4*)&As[buf][kk][ty * 8];
            float4 a1 = *(const float4*)&As[buf][kk][ty * 8 + 4];
            u64 bp0 = *(const u64*)&Bs[buf][kk][tx * 8 + 0];
            u64 bp1 = *(const u64*)&Bs[buf][kk][tx * 8 + 2];
            u64 bp2 = *(const u64*)&Bs[buf][kk][tx * 8 + 4];
            u64 bp3 = *(const u64*)&Bs[buf][kk][tx * 8 + 6];
            float av[8] = {a0.x, a0.y, a0.z, a0.w, a1.x, a1.y, a1.z, a1.w};
            #pragma unroll
            for (int r = 0; r < 8; r++) {
                u64 as2 = splat_f32x2(av[r]);
                ffma2(acc[r][0], as2, bp0);
                ffma2(acc[r][1], as2, bp1);
                ffma2(acc[r][2], as2, bp2);
                ffma2(acc[r][3], as2, bp3);
            }
        }

        if (more) {
            const int nbuf = buf ^ 1;
            As[nbuf][acol + 0][arow] = aNext.x;
            As[nbuf][acol + 1][arow] = aNext.y;
            As[nbuf][acol + 2][arow] = aNext.z;
            As[nbuf][acol + 3][arow] = aNext.w;
            *(float4*)&Bs[nbuf][brow][bcol] = bNext;
        }
        __syncthreads();
    }

    // ---- epilogue: BN + ReLU, vectorized stores ----
    #pragma unroll
    for (int r = 0; r < 8; r++) {
        const int m = m0 + ty * 8 + r;
        const float sc = gamma[m] / sqrtf(var[m] + 1e-5f);
        const float bi = beta[m] - mean[m] * sc;
        float o[8];
        #pragma unroll
        for (int p = 0; p < 4; p++) {
            float2 v = unpack_f32x2(acc[r][p]);
            o[2*p + 0] = fmaxf(fmaf(v.x, sc, bi), 0.0f);
            o[2*p + 1] = fmaxf(fmaf(v.y, sc, bi), 0.0f);
        }
        float* dst = Cb + (size_t)m * N + n0 + tx * 8;
        *(float4*)(dst + 0) = make_float4(o[0], o[1], o[2], o[3]);
        *(float4*)(dst + 4) = make_float4(o[4], o[5], o[6], o[7]);
    }
}

// ============================================================================
// launch
// ============================================================================
extern "C" void kernel_launch(void* const* d_in, const int* in_sizes, int n_in,
                              void* d_out, int out_size)
{
    const float* unknown     = (const float*)d_in[0];   // (B,N,3)
    const float* known       = (const float*)d_in[1];   // (B,M,3)
    const float* unknow_feats= (const float*)d_in[2];   // (B,256,N)
    const float* known_feats = (const float*)d_in[3];   // (B,256,M)
    const float* W1 = (const float*)d_in[4];
    const float* g1 = (const float*)d_in[5];
    const float* b1 = (const float*)d_in[6];
    const float* m1 = (const float*)d_in[7];
    const float* v1 = (const float*)d_in[8];
    const float* W2 = (const float*)d_in[9];
    const float* g2 = (const float*)d_in[10];
    const float* b2 = (const float*)d_in[11];
    const float* m2 = (const float*)d_in[12];
    const float* v2 = (const float*)d_in[13];
    float* out = (float*)d_out;

    float* p_interp = nullptr;
    float* p_hidden = nullptr;
    int*   p_idx    = nullptr;
    float* p_w      = nullptr;
    cudaGetSymbolAddress((void**)&p_interp, g_interp);
    cudaGetSymbolAddress((void**)&p_hidden, g_hidden);
    cudaGetSymbolAddress((void**)&p_idx,    g_idx);
    cudaGetSymbolAddress((void**)&p_w,      g_w);

    knn3_kernel<<<dim3(NN / 256, BB), 256>>>(unknown, known, p_idx, p_w);
    interp_kernel<<<dim3(NN / 256, BB), 256>>>(known_feats, p_idx, p_w, p_interp);

    dim3 ggrid(NN / TN, HID / TM, BB);
    // layer 1: rows 0..255 = interpolated feats, rows 256..511 = unknow_feats
    gemm_bn_relu_kernel<<<ggrid, 256>>>(W1,
                                        p_interp, unknow_feats,
                                        (size_t)C2 * NN, (size_t)C1 * NN,
                                        g1, b1, m1, v1, p_hidden);
    // layer 2: both halves from hidden (per-batch stride 512*N)
    gemm_bn_relu_kernel<<<ggrid, 256>>>(W2,
                                        p_hidden, p_hidden + (size_t)256 * NN,
                                        (size_t)HID * NN, (size_t)HID * NN,
                                        g2, b2, m2, v2, out);
}

// round 10
// speedup vs baseline: 1.9544x; 1.9544x over previous
#include <cuda_runtime.h>
#include <cuda_bf16.h>
#include <math.h>
#include <stdint.h>

// Problem constants (fixed by reference setup_inputs)
#define BB   8
#define NN   8192
#define MM   2048
#define C1   256
#define C2   256
#define CIN  512
#define HID  512

// ---------------------------------------------------------------------------
// Scratch (device globals; allocations forbidden)
// ---------------------------------------------------------------------------
__device__ __nv_bfloat16 g_X1hi[(size_t)BB * CIN * NN];
__device__ __nv_bfloat16 g_X1lo[(size_t)BB * CIN * NN];
__device__ __nv_bfloat16 g_Hhi [(size_t)BB * HID * NN];
__device__ __nv_bfloat16 g_Hlo [(size_t)BB * HID * NN];
__device__ __nv_bfloat16 g_W1hi[HID * CIN], g_W1lo[HID * CIN];
__device__ __nv_bfloat16 g_W2hi[HID * HID], g_W2lo[HID * HID];
__device__ int   g_idx[(size_t)BB * NN * 3];
__device__ float g_w  [(size_t)BB * NN * 3];

// ---------------------------------------------------------------------------
// PTX helpers — ONLY baseline (sm_80+) features; compute_103-safe
// ---------------------------------------------------------------------------
__device__ __forceinline__ uint32_t smem_u32(const void* p) {
    uint32_t a;
    asm("{ .reg .u64 t; cvta.to.shared.u64 t, %1; cvt.u32.u64 %0, t; }"
        : "=r"(a) : "l"(p));
    return a;
}
__device__ __forceinline__ void cp_async16(uint32_t dst, const void* src) {
    asm volatile("cp.async.cg.shared.global [%0], [%1], 16;"
                 :: "r"(dst), "l"(src) : "memory");
}
__device__ __forceinline__ void cp_async_commit() {
    asm volatile("cp.async.commit_group;" ::: "memory");
}
template<int N> __device__ __forceinline__ void cp_async_wait() {
    asm volatile("cp.async.wait_group %0;" :: "n"(N) : "memory");
}
__device__ __forceinline__ void ldsm4(uint32_t& r0, uint32_t& r1, uint32_t& r2, uint32_t& r3,
                                      uint32_t a) {
    asm volatile("ldmatrix.sync.aligned.m8n8.x4.shared.b16 {%0,%1,%2,%3}, [%4];"
                 : "=r"(r0), "=r"(r1), "=r"(r2), "=r"(r3) : "r"(a));
}
__device__ __forceinline__ void ldsm4t(uint32_t& r0, uint32_t& r1, uint32_t& r2, uint32_t& r3,
                                       uint32_t a) {
    asm volatile("ldmatrix.sync.aligned.m8n8.x4.trans.shared.b16 {%0,%1,%2,%3}, [%4];"
                 : "=r"(r0), "=r"(r1), "=r"(r2), "=r"(r3) : "r"(a));
}
__device__ __forceinline__ void mma16816(float* c, const uint32_t* a, const uint32_t* b) {
    asm volatile("mma.sync.aligned.m16n8k16.row.col.f32.bf16.bf16.f32 "
                 "{%0,%1,%2,%3}, {%4,%5,%6,%7}, {%8,%9}, {%0,%1,%2,%3};"
                 : "+f"(c[0]), "+f"(c[1]), "+f"(c[2]), "+f"(c[3])
                 : "r"(a[0]), "r"(a[1]), "r"(a[2]), "r"(a[3]),
                   "r"(b[0]), "r"(b[1]));
}

// ---------------------------------------------------------------------------
// Kernel 1: brute-force 3-NN + inverse-distance weights (validated in R3)
// ---------------------------------------------------------------------------
__global__ __launch_bounds__(256)
void knn3_kernel(const float* __restrict__ unknown, const float* __restrict__ known,
                 int* __restrict__ oidx, float* __restrict__ ow)
{
    __shared__ float sx[MM], sy[MM], sz[MM];
    const int b = blockIdx.y;
    const int i = blockIdx.x * 256 + threadIdx.x;

    const float* kb = known + (size_t)b * MM * 3;
    for (int j = threadIdx.x; j < MM; j += 256) {
        sx[j] = kb[j*3 + 0]; sy[j] = kb[j*3 + 1]; sz[j] = kb[j*3 + 2];
    }
    __syncthreads();

    const float* ub = unknown + ((size_t)b * NN + i) * 3;
    const float ux = ub[0], uy = ub[1], uz = ub[2];

    float d0 = 1e30f, d1 = 1e30f, d2 = 1e30f;
    int   j0 = 0,     j1 = 0,     j2 = 0;

    #pragma unroll 4
    for (int j = 0; j < MM; j++) {
        float dx = __fsub_rn(sx[j], ux);
        float dy = __fsub_rn(sy[j], uy);
        float dz = __fsub_rn(sz[j], uz);
        float d  = __fadd_rn(__fadd_rn(__fmul_rn(dx, dx), __fmul_rn(dy, dy)),
                             __fmul_rn(dz, dz));
        if (d < d2) {
            if (d < d1) {
                d2 = d1; j2 = j1;
                if (d < d0) { d1 = d0; j1 = j0; d0 = d; j0 = j; }
                else        { d1 = d;  j1 = j; }
            } else { d2 = d; j2 = j; }
        }
    }

    float r0 = 1.0f / (d0 + 1e-8f);
    float r1 = 1.0f / (d1 + 1e-8f);
    float r2 = 1.0f / (d2 + 1e-8f);
    float s  = (r0 + r1) + r2;

    size_t base = ((size_t)b * NN + i) * 3;
    oidx[base + 0] = j0;  oidx[base + 1] = j1;  oidx[base + 2] = j2;
    ow[base + 0] = r0 / s;  ow[base + 1] = r1 / s;  ow[base + 2] = r2 / s;
}

// ---------------------------------------------------------------------------
// Kernel 2: three_interpolate -> X1 rows [0,256) as bf16 hi/lo
// ---------------------------------------------------------------------------
__global__ __launch_bounds__(256)
void interp_hilo_kernel(const float* __restrict__ kf,
                        const int* __restrict__ gidx, const float* __restrict__ gw,
                        __nv_bfloat16* __restrict__ Xhi, __nv_bfloat16* __restrict__ Xlo)
{
    const int b = blockIdx.y;
    const int i = blockIdx.x * 256 + threadIdx.x;

    size_t base = ((size_t)b * NN + i) * 3;
    const int   i0 = gidx[base], i1 = gidx[base + 1], i2 = gidx[base + 2];
    const float w0 = gw[base],   w1 = gw[base + 1],   w2 = gw[base + 2];

    const float* kfb = kf + (size_t)b * C2 * MM;
    size_t ob = (size_t)b * CIN * NN + i;

    #pragma unroll 4
    for (int c = 0; c < C2; c++) {
        const float* row = kfb + (size_t)c * MM;
        float v = w0 * row[i0] + w1 * row[i1] + w2 * row[i2];
        __nv_bfloat16 h = __float2bfloat16(v);
        Xhi[ob + (size_t)c * NN] = h;
        Xlo[ob + (size_t)c * NN] = __float2bfloat16(v - __bfloat162float(h));
    }
}

// ---------------------------------------------------------------------------
// Kernel 3: unknow_feats -> X1 rows [256,512) as bf16 hi/lo
// ---------------------------------------------------------------------------
__global__ __launch_bounds__(256)
void conv_unknow_kernel(const float* __restrict__ src,
                        __nv_bfloat16* __restrict__ Xhi, __nv_bfloat16* __restrict__ Xlo)
{
    size_t i = (size_t)blockIdx.x * 256 + threadIdx.x;
    const size_t per_b = (size_t)C1 * NN;
    size_t b = i / per_b, rem = i - b * per_b;
    size_t dst = ((size_t)b * CIN + C1) * NN + rem;
    float v = src[i];
    __nv_bfloat16 h = __float2bfloat16(v);
    Xhi[dst] = h;
    Xlo[dst] = __float2bfloat16(v - __bfloat162float(h));
}

// ---------------------------------------------------------------------------
// Kernel 4: generic fp32 -> (hi, lo) bf16 split (W1, W2)
// ---------------------------------------------------------------------------
__global__ __launch_bounds__(256)
void conv_hilo_kernel(const float* __restrict__ src,
                      __nv_bfloat16* __restrict__ hi, __nv_bfloat16* __restrict__ lo, int n)
{
    int i = blockIdx.x * 256 + threadIdx.x;
    if (i < n) {
        float v = src[i];
        __nv_bfloat16 h = __float2bfloat16(v);
        hi[i] = h;
        lo[i] = __float2bfloat16(v - __bfloat162float(h));
    }
}

// ---------------------------------------------------------------------------
// Kernel 5: warp-MMA (mma.sync bf16) split-precision GEMM + BN + ReLU
//   CTA tile 128x128, 8 warps of 64x32, BK=32, K' = 1536 (3 terms x 512).
//   A = W [M,K] K-major smem (row stride 80B).  B = X [K,N] rows in smem
//   (row stride 272B), ldmatrix.x4.trans gives the col-major B fragments.
//   cp.async double-buffered.  Epilogue: BN+ReLU -> smem stage -> coalesced.
//   MODE 0: emits bf16 hi/lo pair (feeds layer 2);  MODE 1: fp32 output.
// ---------------------------------------------------------------------------
#define A_STRIDE   80      // 64B row + 16B pad
#define B_STRIDE   272     // 256B row + 16B pad
#define A_BUF      (128 * A_STRIDE)          // 10240
#define B_BUF      (32 * B_STRIDE)           // 8704
#define SB_OFF     (2 * A_BUF)               // 20480
#define SMEM_BYTES 66560                     // stage 128x129 fp32 dominates
#define NCHUNK     48

template<int MODE>
__global__ __launch_bounds__(256)
void gemm_mma_kernel(const __nv_bfloat16* __restrict__ Whi, const __nv_bfloat16* __restrict__ Wlo,
                     const __nv_bfloat16* __restrict__ Xhi, const __nv_bfloat16* __restrict__ Xlo,
                     const float* __restrict__ gamma, const float* __restrict__ beta,
                     const float* __restrict__ mean,  const float* __restrict__ var,
                     float* __restrict__ outF,
                     __nv_bfloat16* __restrict__ outHi, __nv_bfloat16* __restrict__ outLo)
{
    extern __shared__ char smem[];
    const uint32_t sbase = smem_u32(smem);
    const uint32_t sA = sbase;
    const uint32_t sB = sbase + SB_OFF;
    float* stage = (float*)smem;             // reused after the k-loop

    const int tid  = threadIdx.x;
    const int b    = blockIdx.z;
    const int m0   = blockIdx.x * 128;
    const int n0   = blockIdx.y * 128;
    const int wid  = tid >> 5, lane = tid & 31;
    const int wm   = wid >> 2, wn = wid & 3;          // warp grid 2 x 4

    // ldmatrix lane base addresses (buffer-relative)
    const uint32_t a_base = sA + (uint32_t)(wm * 64 + (lane & 15)) * A_STRIDE
                          + (uint32_t)(lane >> 4) * 16;
    const uint32_t b_base = sB + (uint32_t)(lane & 15) * B_STRIDE
                          + (uint32_t)(wn * 32 + (lane >> 4) * 8) * 2;

    // ---- async chunk loader ----
    auto load_chunk = [&](int kc, int buf) {
        const __nv_bfloat16* Wsel = (kc < 32) ? Whi : Wlo;
        const __nv_bfloat16* Xsel = (kc >= 16 && kc < 32) ? Xlo : Xhi;
        const int k_in = (kc & 15) * 32;
        #pragma unroll
        for (int i = 0; i < 2; i++) {        // A: 128 rows x 4 x 16B
            int t = tid + i * 256;
            int r = t >> 2, seg = t & 3;
            cp_async16(sA + buf * A_BUF + r * A_STRIDE + seg * 16,
                       Wsel + (size_t)(m0 + r) * CIN + k_in + seg * 8);
        }
        #pragma unroll
        for (int i = 0; i < 2; i++) {        // B: 32 rows x 16 x 16B
            int t = tid + i * 256;
            int r = t >> 4, seg = t & 15;
            cp_async16(sB + buf * B_BUF + r * B_STRIDE + seg * 16,
                       Xsel + ((size_t)b * CIN + k_in + r) * NN + n0 + seg * 8);
        }
        cp_async_commit();
    };

    float acc[4][4][4];
    #pragma unroll
    for (int mt = 0; mt < 4; mt++)
        #pragma unroll
        for (int nt = 0; nt < 4; nt++)
            #pragma unroll
            for (int p = 0; p < 4; p++) acc[mt][nt][p] = 0.0f;

    load_chunk(0, 0);
    load_chunk(1, 1);

    for (int kc = 0; kc < NCHUNK; kc++) {
        const int buf = kc & 1;
        if (kc == NCHUNK - 1) cp_async_wait<0>(); else cp_async_wait<1>();
        __syncthreads();

        const uint32_t aBufBase = a_base + buf * A_BUF;
        const uint32_t bBufBase = b_base + buf * B_BUF;
        #pragma unroll
        for (int ks = 0; ks < 2; ks++) {
            uint32_t af[4][4];
            #pragma unroll
            for (int mt = 0; mt < 4; mt++)
                ldsm4(af[mt][0], af[mt][1], af[mt][2], af[mt][3],
                      aBufBase + mt * (16 * A_STRIDE) + ks * 32);
            uint32_t bf[2][4];
            #pragma unroll
            for (int nh = 0; nh < 2; nh++)
                ldsm4t(bf[nh][0], bf[nh][1], bf[nh][2], bf[nh][3],
                       bBufBase + ks * (16 * B_STRIDE) + nh * 32);
            #pragma unroll
            for (int mt = 0; mt < 4; mt++)
                #pragma unroll
                for (int nt = 0; nt < 4; nt++)
                    mma16816(acc[mt][nt], af[mt], &bf[nt >> 1][(nt & 1) * 2]);
        }

        __syncthreads();
        if (kc + 2 < NCHUNK) load_chunk(kc + 2, buf);
    }

    // ---- epilogue: BN+ReLU into smem stage (barrier above guarantees all
    //      warps finished reading the tiles; stage overlays sA/sB) ----
    #pragma unroll
    for (int mt = 0; mt < 4; mt++) {
        #pragma unroll
        for (int h2 = 0; h2 < 2; h2++) {
            const int r = wm * 64 + mt * 16 + (lane >> 2) + h2 * 8;
            const int m = m0 + r;
            const float sc = gamma[m] / sqrtf(var[m] + 1e-5f);
            const float bi = beta[m] - mean[m] * sc;
            #pragma unroll
            for (int nt = 0; nt < 4; nt++) {
                const int c = wn * 32 + nt * 8 + (lane & 3) * 2;
                stage[r * 129 + c]     = fmaxf(fmaf(acc[mt][nt][h2 * 2 + 0], sc, bi), 0.0f);
                stage[r * 129 + c + 1] = fmaxf(fmaf(acc[mt][nt][h2 * 2 + 1], sc, bi), 0.0f);
            }
        }
    }
    __syncthreads();

    if (MODE == 0) {
        for (int idx = tid; idx < 128 * 64; idx += 256) {
            int r = idx >> 6, p = idx & 63;
            float v0 = stage[r * 129 + 2 * p];
            float v1 = stage[r * 129 + 2 * p + 1];
            __nv_bfloat16 h0 = __float2bfloat16(v0);
            __nv_bfloat16 h1 = __float2bfloat16(v1);
            __nv_bfloat162 hp; hp.x = h0; hp.y = h1;
            __nv_bfloat162 lp;
            lp.x = __float2bfloat16(v0 - __bfloat162float(h0));
            lp.y = __float2bfloat16(v1 - __bfloat162float(h1));
            size_t dst = ((size_t)b * HID + m0 + r) * NN + n0 + 2 * p;
            *(__nv_bfloat162*)(outHi + dst) = hp;
            *(__nv_bfloat162*)(outLo + dst) = lp;
        }
    } else {
        for (int idx = tid; idx < 128 * 128; idx += 256) {
            int r = idx >> 7, c = idx & 127;
            outF[((size_t)b * HID + m0 + r) * NN + n0 + c] = stage[r * 129 + c];
        }
    }
}

// ---------------------------------------------------------------------------
// launch
// ---------------------------------------------------------------------------
extern "C" void kernel_launch(void* const* d_in, const int* in_sizes, int n_in,
                              void* d_out, int out_size)
{
    const float* unknown      = (const float*)d_in[0];
    const float* known        = (const float*)d_in[1];
    const float* unknow_feats = (const float*)d_in[2];
    const float* known_feats  = (const float*)d_in[3];
    const float* W1 = (const float*)d_in[4];
    const float* g1 = (const float*)d_in[5];
    const float* b1 = (const float*)d_in[6];
    const float* m1 = (const float*)d_in[7];
    const float* v1 = (const float*)d_in[8];
    const float* W2 = (const float*)d_in[9];
    const float* g2 = (const float*)d_in[10];
    const float* b2 = (const float*)d_in[11];
    const float* m2 = (const float*)d_in[12];
    const float* v2 = (const float*)d_in[13];
    float* out = (float*)d_out;

    __nv_bfloat16 *pX1hi, *pX1lo, *pHhi, *pHlo, *pW1hi, *pW1lo, *pW2hi, *pW2lo;
    int* pIdx; float* pW;
    cudaGetSymbolAddress((void**)&pX1hi, g_X1hi);
    cudaGetSymbolAddress((void**)&pX1lo, g_X1lo);
    cudaGetSymbolAddress((void**)&pHhi,  g_Hhi);
    cudaGetSymbolAddress((void**)&pHlo,  g_Hlo);
    cudaGetSymbolAddress((void**)&pW1hi, g_W1hi);
    cudaGetSymbolAddress((void**)&pW1lo, g_W1lo);
    cudaGetSymbolAddress((void**)&pW2hi, g_W2hi);
    cudaGetSymbolAddress((void**)&pW2lo, g_W2lo);
    cudaGetSymbolAddress((void**)&pIdx,  g_idx);
    cudaGetSymbolAddress((void**)&pW,    g_w);

    cudaFuncSetAttribute(gemm_mma_kernel<0>, cudaFuncAttributeMaxDynamicSharedMemorySize, SMEM_BYTES);
    cudaFuncSetAttribute(gemm_mma_kernel<1>, cudaFuncAttributeMaxDynamicSharedMemorySize, SMEM_BYTES);

    // 1. kNN + weights
    knn3_kernel<<<dim3(NN / 256, BB), 256>>>(unknown, known, pIdx, pW);
    // 2. interpolation -> X1 rows [0,256) (hi/lo)
    interp_hilo_kernel<<<dim3(NN / 256, BB), 256>>>(known_feats, pIdx, pW, pX1hi, pX1lo);
    // 3. unknow_feats -> X1 rows [256,512) (hi/lo)
    conv_unknow_kernel<<<(int)(((size_t)BB * C1 * NN) / 256), 256>>>(unknow_feats, pX1hi, pX1lo);
    // 4. weight splits
    conv_hilo_kernel<<<(HID * CIN + 255) / 256, 256>>>(W1, pW1hi, pW1lo, HID * CIN);
    conv_hilo_kernel<<<(HID * HID + 255) / 256, 256>>>(W2, pW2hi, pW2lo, HID * HID);

    // 5. layer 1 (warp MMA), epilogue emits hi/lo bf16 hidden
    dim3 grid(HID / 128, NN / 128, BB);
    gemm_mma_kernel<0><<<grid, 256, SMEM_BYTES>>>(pW1hi, pW1lo, pX1hi, pX1lo,
                                                  g1, b1, m1, v1,
                                                  nullptr, pHhi, pHlo);
    // 6. layer 2, epilogue emits fp32 output
    gemm_mma_kernel<1><<<grid, 256, SMEM_BYTES>>>(pW2hi, pW2lo, pHhi, pHlo,
                                                  g2, b2, m2, v2,
                                                  out, nullptr, nullptr);
}